// round 1
// baseline (speedup 1.0000x reference)
#include <cuda_runtime.h>

// Problem constants
#define Bsz 2
#define Sq  2048
#define HIDN 512
#define NHh 8
#define Dh  64
#define GH  (Bsz*NHh)   // 16 batched (b,h) pairs

// Scratch (allocation-free rule: __device__ globals)
__device__ float g_qh [Bsz*NHh*Sq*Dh];   //  8 MB  [g][s][d]  (pre-scaled by 1/8)
__device__ float g_kh [Bsz*NHh*Sq*Dh];   //  8 MB  [g][s][d]
__device__ float g_vhT[Bsz*NHh*Dh*Sq];   //  8 MB  [g][d][s]
__device__ float g_wT [Bsz*Sq*Sq];       // 32 MB  [b][l][k]
__device__ float g_x  [(long)GH*Sq*Sq];  // 256 MB scores (biased+masked)
__device__ float g_y  [(long)GH*Sq*Sq];  // 256 MB x@w, softmaxed in place
__device__ float g_o  [Bsz*Sq*HIDN];     // 16 MB  [b][s][h*D+d]
__device__ int   g_mask_mode;            // 0=int32/float32 word, 2=uint8 byte

// ---------------------------------------------------------------------------
// Mask dtype sniffer: bool mask may arrive as int32, float32 or uint8.
//   uint8 packing -> words with bytes {0,1} in positions >0 (value>1, !=1.0f)
//   float32      -> words == 0x3F800000
//   int32        -> words in {0,1}
// For word modes (int32/float32) "true" <=> word != 0, so they share a path.
// ---------------------------------------------------------------------------
__global__ void detect_mask_kernel(const unsigned int* __restrict__ m, int nwords) {
    __shared__ int s_multi;
    if (threadIdx.x == 0) s_multi = 0;
    __syncthreads();
    int found = 0;
    for (int i = threadIdx.x; i < nwords; i += blockDim.x) {
        unsigned int v = m[i];
        if (v > 1u && v != 0x3F800000u) found = 1;
    }
    if (found) atomicOr(&s_multi, 1);
    __syncthreads();
    if (threadIdx.x == 0) g_mask_mode = s_multi ? 2 : 0;
}

__device__ __forceinline__ bool mask_true(const void* mask, long idx) {
    if (g_mask_mode == 2) return ((const unsigned char*)mask)[idx] != 0;
    return ((const unsigned int*)mask)[idx] != 0u;  // int32 or float32(1.0f)
}

// ---------------------------------------------------------------------------
// w transpose: g_wT[b][l][k] = w[b][k][l]
// ---------------------------------------------------------------------------
__global__ void transpose_w_kernel(const float* __restrict__ w) {
    __shared__ float t[32][33];
    int b = blockIdx.z;
    int k0 = blockIdx.y * 32, l0 = blockIdx.x * 32;
    const float* wb = w + (long)b * Sq * Sq;
    float* ob = g_wT + (long)b * Sq * Sq;
    int x = threadIdx.x, y = threadIdx.y;  // block (32,8)
    #pragma unroll
    for (int i = 0; i < 32; i += 8)
        t[y + i][x] = wb[(long)(k0 + y + i) * Sq + (l0 + x)];
    __syncthreads();
    #pragma unroll
    for (int i = 0; i < 32; i += 8)
        ob[(long)(l0 + y + i) * Sq + (k0 + x)] = t[x][y + i];
}

// ---------------------------------------------------------------------------
// Generic batched NT SGEMM: C[m,n] = sum_k A[m,k] * B[n,k], 128x128x8 tiles,
// 256 threads, 8x8 microtiles, with per-MODE epilogue.
// ---------------------------------------------------------------------------
#define BM 128
#define BN 128
#define BKK 8
#define TM 8
#define TN 8

enum { EP_QPROJ = 0, EP_KPROJ, EP_VPROJT, EP_SCORES, EP_Y, EP_OGEMM, EP_OUT };

template <int MODE>
__global__ void __launch_bounds__(256)
sgemm_nt(const float* __restrict__ Aarg, const float* __restrict__ Barg,
         float* __restrict__ Cout,
         int M, int N, int K, int lda, int ldb,
         long asb, long bsb, int bdivB,
         const float* __restrict__ bias,
         const float* __restrict__ attn_bias,
         const void* __restrict__ mask)
{
    __shared__ float As[BKK][BM];
    __shared__ float Bs[BKK][BN];

    // Operand selection (device globals can't be addressed from host)
    const float* Aop =
        (MODE == EP_SCORES) ? g_qh :
        (MODE == EP_Y)      ? g_x  :
        (MODE == EP_OGEMM)  ? g_y  :
        (MODE == EP_OUT)    ? g_o  : Aarg;
    const float* Bop =
        (MODE == EP_SCORES) ? g_kh  :
        (MODE == EP_Y)      ? g_wT  :
        (MODE == EP_OGEMM)  ? g_vhT : Barg;

    int g = blockIdx.z;
    const float* Ab = Aop + (long)g * asb;
    const float* Bb = Bop + (long)(g / bdivB) * bsb;

    int m0 = blockIdx.y * BM, n0 = blockIdx.x * BN;
    int tid = threadIdx.x;
    int tx = tid & 15, ty = tid >> 4;

    float acc[TM][TN];
    #pragma unroll
    for (int i = 0; i < TM; i++)
        #pragma unroll
        for (int j = 0; j < TN; j++) acc[i][j] = 0.f;

    int lrow = tid >> 1;          // 0..127
    int lcol = (tid & 1) * 4;     // 0 or 4

    for (int k0 = 0; k0 < K; k0 += BKK) {
        float4 av = make_float4(0.f, 0.f, 0.f, 0.f);
        int gm = m0 + lrow;
        if (gm < M) av = *(const float4*)(Ab + (long)gm * lda + k0 + lcol);
        As[lcol + 0][lrow] = av.x; As[lcol + 1][lrow] = av.y;
        As[lcol + 2][lrow] = av.z; As[lcol + 3][lrow] = av.w;

        float4 bv = make_float4(0.f, 0.f, 0.f, 0.f);
        int gn = n0 + lrow;
        if (gn < N) bv = *(const float4*)(Bb + (long)gn * ldb + k0 + lcol);
        Bs[lcol + 0][lrow] = bv.x; Bs[lcol + 1][lrow] = bv.y;
        Bs[lcol + 2][lrow] = bv.z; Bs[lcol + 3][lrow] = bv.w;

        __syncthreads();
        #pragma unroll
        for (int kk = 0; kk < BKK; kk++) {
            float ra[TM], rb[TN];
            #pragma unroll
            for (int i = 0; i < TM; i++) ra[i] = As[kk][ty * TM + i];
            #pragma unroll
            for (int j = 0; j < TN; j++) rb[j] = Bs[kk][tx * TN + j];
            #pragma unroll
            for (int i = 0; i < TM; i++)
                #pragma unroll
                for (int j = 0; j < TN; j++) acc[i][j] += ra[i] * rb[j];
        }
        __syncthreads();
    }

    // Epilogue
    #pragma unroll
    for (int i = 0; i < TM; i++) {
        int m = m0 + ty * TM + i;
        if (m >= M) continue;
        #pragma unroll
        for (int j = 0; j < TN; j++) {
            int n = n0 + tx * TN + j;
            if (n >= N) continue;
            float v = acc[i][j];
            if (MODE == EP_QPROJ) {
                v = (v + bias[n]) * 0.125f;   // fold scale = D^-0.5 = 1/8
                int b_ = m / Sq, s = m % Sq, h = n / Dh, d = n % Dh;
                g_qh[(((long)(b_ * NHh + h)) * Sq + s) * Dh + d] = v;
            } else if (MODE == EP_KPROJ) {
                v += bias[n];
                int b_ = m / Sq, s = m % Sq, h = n / Dh, d = n % Dh;
                g_kh[(((long)(b_ * NHh + h)) * Sq + s) * Dh + d] = v;
            } else if (MODE == EP_VPROJT) {
                v += bias[n];
                int b_ = m / Sq, s = m % Sq, h = n / Dh, d = n % Dh;
                g_vhT[(((long)(b_ * NHh + h)) * Dh + d) * Sq + s] = v;
            } else if (MODE == EP_SCORES) {
                int b_ = g / NHh;
                long idx  = (long)g  * Sq * Sq + (long)m * Sq + n;
                long midx = (long)b_ * Sq * Sq + (long)m * Sq + n;
                v += attn_bias[idx];
                if (mask_true(mask, midx)) v = 0.f;
                g_x[idx] = v;
            } else if (MODE == EP_Y) {
                g_y[(long)g * Sq * Sq + (long)m * Sq + n] = v;
            } else if (MODE == EP_OGEMM) {
                int b_ = g / NHh, h = g % NHh;
                g_o[((long)(b_ * Sq + m)) * HIDN + h * Dh + n] = v;
            } else {  // EP_OUT
                v += bias[n];
                Cout[(long)m * N + n] = v;
            }
        }
    }
}

// ---------------------------------------------------------------------------
// Row softmax over g_y (GH*Sq rows of length Sq), in place
// ---------------------------------------------------------------------------
__global__ void softmax_rows_kernel() {
    float* p = g_y + (long)blockIdx.x * Sq;
    __shared__ float red[256];
    int t = threadIdx.x;

    float mx = -3.0e38f;
    for (int i = t; i < Sq; i += 256) mx = fmaxf(mx, p[i]);
    red[t] = mx; __syncthreads();
    for (int s = 128; s > 0; s >>= 1) {
        if (t < s) red[t] = fmaxf(red[t], red[t + s]);
        __syncthreads();
    }
    mx = red[0];
    __syncthreads();

    float sum = 0.f;
    for (int i = t; i < Sq; i += 256) {
        float e = expf(p[i] - mx);
        p[i] = e;
        sum += e;
    }
    red[t] = sum; __syncthreads();
    for (int s = 128; s > 0; s >>= 1) {
        if (t < s) red[t] += red[t + s];
        __syncthreads();
    }
    float inv = 1.f / red[0];
    for (int i = t; i < Sq; i += 256) p[i] *= inv;
}

// ---------------------------------------------------------------------------
extern "C" void kernel_launch(void* const* d_in, const int* in_sizes, int n_in,
                              void* d_out, int out_size)
{
    const float* q    = (const float*)d_in[0];
    const float* k    = (const float*)d_in[1];
    const float* v    = (const float*)d_in[2];
    const float* ab   = (const float*)d_in[3];
    const void*  mask = d_in[4];
    const float* w    = (const float*)d_in[5];
    const float* Wq   = (const float*)d_in[6];
    const float* bq   = (const float*)d_in[7];
    const float* Wk   = (const float*)d_in[8];
    const float* bk   = (const float*)d_in[9];
    const float* Wv   = (const float*)d_in[10];
    const float* bv   = (const float*)d_in[11];
    const float* Wo   = (const float*)d_in[12];
    const float* bo   = (const float*)d_in[13];
    float* out = (float*)d_out;

    detect_mask_kernel<<<1, 256>>>((const unsigned int*)mask, 65536);
    transpose_w_kernel<<<dim3(64, 64, Bsz), dim3(32, 8)>>>(w);

    const int M1 = Bsz * Sq;  // 4096
    // QKV projections: [4096,512] @ [512,512]^T
    sgemm_nt<EP_QPROJ><<<dim3(4, 32, 1), 256>>>(q, Wq, nullptr,
        M1, HIDN, HIDN, HIDN, HIDN, 0, 0, 1, bq, nullptr, nullptr);
    sgemm_nt<EP_KPROJ><<<dim3(4, 32, 1), 256>>>(k, Wk, nullptr,
        M1, HIDN, HIDN, HIDN, HIDN, 0, 0, 1, bk, nullptr, nullptr);
    sgemm_nt<EP_VPROJT><<<dim3(4, 32, 1), 256>>>(v, Wv, nullptr,
        M1, HIDN, HIDN, HIDN, HIDN, 0, 0, 1, bv, nullptr, nullptr);

    // Scores: per (b,h): [2048,64] @ [2048,64]^T + bias, masked -> g_x
    sgemm_nt<EP_SCORES><<<dim3(16, 16, GH), 256>>>(nullptr, nullptr, nullptr,
        Sq, Sq, Dh, Dh, Dh, (long)Sq * Dh, (long)Sq * Dh, 1,
        nullptr, ab, mask);

    // y = x @ w (dominant): per (b,h): [2048,2048] @ [2048,2048]
    sgemm_nt<EP_Y><<<dim3(16, 16, GH), 256>>>(nullptr, nullptr, nullptr,
        Sq, Sq, Sq, Sq, Sq, (long)Sq * Sq, (long)Sq * Sq, NHh,
        nullptr, nullptr, nullptr);

    // Softmax rows of g_y in place
    softmax_rows_kernel<<<GH * Sq, 256>>>();

    // o = p @ vh: per (b,h): [2048,2048] @ [64,2048]^T -> g_o[b][s][h*D+d]
    sgemm_nt<EP_OGEMM><<<dim3(1, 16, GH), 256>>>(nullptr, nullptr, nullptr,
        Sq, Dh, Sq, Sq, Sq, (long)Sq * Sq, (long)Dh * Sq, 1,
        nullptr, nullptr, nullptr);

    // out = g_o @ Wo^T + bo
    sgemm_nt<EP_OUT><<<dim3(4, 32, 1), 256>>>(nullptr, Wo, out,
        M1, HIDN, HIDN, HIDN, HIDN, 0, 0, 1, bo, nullptr, nullptr);
}

// round 3
// speedup vs baseline: 2.4280x; 2.4280x over previous
#include <cuda_runtime.h>
#include <cuda_fp16.h>
#include <cstdint>

// Problem constants
#define Bsz 2
#define Sq  2048
#define HIDN 512
#define NHh 8
#define Dh  64
#define GH  (Bsz*NHh)   // 16 batched (b,h) pairs

// Scratch (allocation-free rule: __device__ globals)
__device__ __align__(128) float  g_qh [Bsz*NHh*Sq*Dh];      //  8 MB [g][s][d] (pre-scaled)
__device__ __align__(128) float  g_kh [Bsz*NHh*Sq*Dh];      //  8 MB [g][s][d]
__device__ __align__(128) float  g_vhT[Bsz*NHh*Dh*Sq];      //  8 MB [g][d][s]
__device__ __align__(128) __half g_xh [(long)GH*Sq*Sq];     // 128 MB scores fp16 [g][m][k]
__device__ __align__(128) __half g_wTh[(long)Bsz*Sq*Sq];    //  16 MB w^T fp16 [b][l][k]
__device__ __align__(128) float  g_y  [(long)GH*Sq*Sq];     // 256 MB y = x@w, softmaxed in place
__device__ __align__(128) float  g_o  [Bsz*Sq*HIDN];        //  16 MB [b][s][h*D+d]
__device__ int   g_mask_mode;

// ---------------------------------------------------------------------------
// Mask dtype sniffer
// ---------------------------------------------------------------------------
__global__ void detect_mask_kernel(const unsigned int* __restrict__ m, int nwords) {
    __shared__ int s_multi;
    if (threadIdx.x == 0) s_multi = 0;
    __syncthreads();
    int found = 0;
    for (int i = threadIdx.x; i < nwords; i += blockDim.x) {
        unsigned int v = m[i];
        if (v > 1u && v != 0x3F800000u) found = 1;
    }
    if (found) atomicOr(&s_multi, 1);
    __syncthreads();
    if (threadIdx.x == 0) g_mask_mode = s_multi ? 2 : 0;
}

__device__ __forceinline__ bool mask_true(const void* mask, long idx) {
    if (g_mask_mode == 2) return ((const unsigned char*)mask)[idx] != 0;
    return ((const unsigned int*)mask)[idx] != 0u;
}

// ---------------------------------------------------------------------------
// w transpose -> fp16: g_wTh[b][l][k] = half(w[b][k][l])
// ---------------------------------------------------------------------------
__global__ void transpose_w_kernel(const float* __restrict__ w) {
    __shared__ float t[32][33];
    int b = blockIdx.z;
    int k0 = blockIdx.y * 32, l0 = blockIdx.x * 32;
    const float* wb = w + (long)b * Sq * Sq;
    __half* ob = g_wTh + (long)b * Sq * Sq;
    int x = threadIdx.x, y = threadIdx.y;  // block (32,8)
    #pragma unroll
    for (int i = 0; i < 32; i += 8)
        t[y + i][x] = wb[(long)(k0 + y + i) * Sq + (l0 + x)];
    __syncthreads();
    #pragma unroll
    for (int i = 0; i < 32; i += 8)
        ob[(long)(l0 + y + i) * Sq + (k0 + x)] = __float2half(t[x][y + i]);
}

// ===========================================================================
// HMMA fp16 GEMM for y = x @ w (dominant stage): per head g,
//   C[2048,2048](f32) = A[2048,2048](f16) x B[2048,2048](f16)^T  (NT)
// CTA 128x128x32, 8 warps (2x4), warp tile 64x32, 3-stage cp.async, SW64.
// ===========================================================================
#define XBM 128
#define XBN 128
#define XBK 32
#define XNST 3
#define XKIT (Sq/XBK)                 // 64
#define XSTAGE 16384                  // (128+128)*64B

static __device__ __forceinline__ uint32_t sw64(uint32_t x) { return x ^ ((x >> 3) & 0x30); }

__device__ __forceinline__ void cp_async16(uint32_t saddr, const void* gaddr) {
    asm volatile("cp.async.cg.shared.global [%0], [%1], 16;"
                 :: "r"(saddr), "l"(gaddr) : "memory");
}

__device__ __forceinline__ void ldsm_x4(uint32_t* r, uint32_t addr) {
    asm volatile("ldmatrix.sync.aligned.m8n8.x4.shared.b16 {%0,%1,%2,%3}, [%4];"
                 : "=r"(r[0]), "=r"(r[1]), "=r"(r[2]), "=r"(r[3]) : "r"(addr));
}
__device__ __forceinline__ void ldsm_x2(uint32_t* r, uint32_t addr) {
    asm volatile("ldmatrix.sync.aligned.m8n8.x2.shared.b16 {%0,%1}, [%2];"
                 : "=r"(r[0]), "=r"(r[1]) : "r"(addr));
}
__device__ __forceinline__ void mma16816(float* c, const uint32_t* a, const uint32_t* b) {
    asm volatile(
        "mma.sync.aligned.m16n8k16.row.col.f32.f16.f16.f32 "
        "{%0,%1,%2,%3}, {%4,%5,%6,%7}, {%8,%9}, {%0,%1,%2,%3};"
        : "+f"(c[0]), "+f"(c[1]), "+f"(c[2]), "+f"(c[3])
        : "r"(a[0]), "r"(a[1]), "r"(a[2]), "r"(a[3]), "r"(b[0]), "r"(b[1]));
}

__global__ void __launch_bounds__(256) xw_mma_kernel() {
    __shared__ __align__(128) char smem[XNST * XSTAGE];   // 48 KB
    uint32_t sbase = (uint32_t)__cvta_generic_to_shared(smem);

    int tid = threadIdx.x;
    int wid = tid >> 5, lane = tid & 31;
    int wm = (wid >> 2) * 64;        // warp m offset (0,64)
    int wn = (wid & 3) * 32;         // warp n offset (0..96)

    int g  = blockIdx.z;
    int m0 = blockIdx.y * XBM;
    int n0 = blockIdx.x * XBN;
    const __half* Ag = g_xh  + (long)g        * Sq * Sq + (long)m0 * Sq;
    const __half* Bg = g_wTh + (long)(g >> 3) * Sq * Sq + (long)n0 * Sq;

    float c[4][4][4];
    #pragma unroll
    for (int t = 0; t < 4; t++)
        #pragma unroll
        for (int u = 0; u < 4; u++)
            #pragma unroll
            for (int i = 0; i < 4; i++) c[t][u][i] = 0.f;

    // stage loader: A 128 rows x 64B + B 128 rows x 64B, 4 chunks/row, SW64
    auto load_stage = [&](int st, int kt) {
        uint32_t base = sbase + st * XSTAGE;
        const char* Ak = (const char*)(Ag + kt * XBK);
        const char* Bk = (const char*)(Bg + kt * XBK);
        #pragma unroll
        for (int it = 0; it < 4; it++) {
            int t = tid + it * 256;              // 0..1023
            int r = (t & 511) >> 2, ch = t & 3;
            uint32_t so = sw64(r * 64 + ch * 16);
            if (t < 512)
                cp_async16(base + so, Ak + (long)r * (Sq * 2) + ch * 16);
            else
                cp_async16(base + 8192 + so, Bk + (long)r * (Sq * 2) + ch * 16);
        }
    };

    load_stage(0, 0);
    asm volatile("cp.async.commit_group;" ::: "memory");
    load_stage(1, 1);
    asm volatile("cp.async.commit_group;" ::: "memory");

    for (int k = 0; k < XKIT; k++) {
        int st = k % XNST;
        asm volatile("cp.async.wait_group 1;" ::: "memory");
        __syncthreads();

        int kn = k + 2;
        if (kn < XKIT) load_stage(kn % XNST, kn);
        asm volatile("cp.async.commit_group;" ::: "memory");

        uint32_t abase = sbase + st * XSTAGE;
        uint32_t bbase = abase + 8192;
        #pragma unroll
        for (int ks = 0; ks < 2; ks++) {
            uint32_t a[4][4], b[4][2];
            #pragma unroll
            for (int t = 0; t < 4; t++) {
                int row = wm + t * 16 + (lane & 15);
                uint32_t addr = abase + sw64(row * 64 + ks * 32 + (lane >> 4) * 16);
                ldsm_x4(a[t], addr);
            }
            #pragma unroll
            for (int u = 0; u < 4; u++) {
                int row = wn + u * 8 + (lane & 7);
                uint32_t addr = bbase + sw64(row * 64 + ks * 32 + ((lane >> 3) & 1) * 16);
                ldsm_x2(b[u], addr);
            }
            #pragma unroll
            for (int t = 0; t < 4; t++)
                #pragma unroll
                for (int u = 0; u < 4; u++)
                    mma16816(c[t][u], a[t], b[u]);
        }
    }

    // epilogue -> g_y fp32
    float* Cg = g_y + (long)g * Sq * Sq;
    #pragma unroll
    for (int t = 0; t < 4; t++) {
        int m = m0 + wm + t * 16 + (lane >> 2);
        #pragma unroll
        for (int u = 0; u < 4; u++) {
            int n = n0 + wn + u * 8 + (lane & 3) * 2;
            float* p = Cg + (long)m * Sq + n;
            p[0] = c[t][u][0]; p[1] = c[t][u][1];
            p[8 * Sq] = c[t][u][2]; p[8 * Sq + 1] = c[t][u][3];
        }
    }
}

// ---------------------------------------------------------------------------
// Generic batched NT SGEMM (fp32 SIMT) for the small stages
// ---------------------------------------------------------------------------
#define BM 128
#define BN 128
#define BKK 8
#define TM 8
#define TN 8

enum { EP_QPROJ = 0, EP_KPROJ, EP_VPROJT, EP_SCORES, EP_OGEMM, EP_OUT };

template <int MODE>
__global__ void __launch_bounds__(256)
sgemm_nt(const float* __restrict__ Aarg, const float* __restrict__ Barg,
         float* __restrict__ Cout,
         int M, int N, int K, int lda, int ldb,
         long asb, long bsb, int bdivB,
         const float* __restrict__ bias,
         const float* __restrict__ attn_bias,
         const void* __restrict__ mask)
{
    __shared__ float As[BKK][BM];
    __shared__ float Bs[BKK][BN];

    const float* Aop =
        (MODE == EP_SCORES) ? g_qh :
        (MODE == EP_OGEMM)  ? g_y  :
        (MODE == EP_OUT)    ? g_o  : Aarg;
    const float* Bop =
        (MODE == EP_SCORES) ? g_kh  :
        (MODE == EP_OGEMM)  ? g_vhT : Barg;

    int g = blockIdx.z;
    const float* Ab = Aop + (long)g * asb;
    const float* Bb = Bop + (long)(g / bdivB) * bsb;

    int m0 = blockIdx.y * BM, n0 = blockIdx.x * BN;
    int tid = threadIdx.x;
    int tx = tid & 15, ty = tid >> 4;

    float acc[TM][TN];
    #pragma unroll
    for (int i = 0; i < TM; i++)
        #pragma unroll
        for (int j = 0; j < TN; j++) acc[i][j] = 0.f;

    int lrow = tid >> 1;
    int lcol = (tid & 1) * 4;

    for (int k0 = 0; k0 < K; k0 += BKK) {
        float4 av = make_float4(0.f, 0.f, 0.f, 0.f);
        int gm = m0 + lrow;
        if (gm < M) av = *(const float4*)(Ab + (long)gm * lda + k0 + lcol);
        As[lcol + 0][lrow] = av.x; As[lcol + 1][lrow] = av.y;
        As[lcol + 2][lrow] = av.z; As[lcol + 3][lrow] = av.w;

        float4 bv = make_float4(0.f, 0.f, 0.f, 0.f);
        int gn = n0 + lrow;
        if (gn < N) bv = *(const float4*)(Bb + (long)gn * ldb + k0 + lcol);
        Bs[lcol + 0][lrow] = bv.x; Bs[lcol + 1][lrow] = bv.y;
        Bs[lcol + 2][lrow] = bv.z; Bs[lcol + 3][lrow] = bv.w;

        __syncthreads();
        #pragma unroll
        for (int kk = 0; kk < BKK; kk++) {
            float ra[TM], rb[TN];
            #pragma unroll
            for (int i = 0; i < TM; i++) ra[i] = As[kk][ty * TM + i];
            #pragma unroll
            for (int j = 0; j < TN; j++) rb[j] = Bs[kk][tx * TN + j];
            #pragma unroll
            for (int i = 0; i < TM; i++)
                #pragma unroll
                for (int j = 0; j < TN; j++) acc[i][j] += ra[i] * rb[j];
        }
        __syncthreads();
    }

    #pragma unroll
    for (int i = 0; i < TM; i++) {
        int m = m0 + ty * TM + i;
        if (m >= M) continue;
        #pragma unroll
        for (int j = 0; j < TN; j++) {
            int n = n0 + tx * TN + j;
            if (n >= N) continue;
            float v = acc[i][j];
            if (MODE == EP_QPROJ) {
                v = (v + bias[n]) * 0.125f;
                int b_ = m / Sq, s = m % Sq, h = n / Dh, d = n % Dh;
                g_qh[(((long)(b_ * NHh + h)) * Sq + s) * Dh + d] = v;
            } else if (MODE == EP_KPROJ) {
                v += bias[n];
                int b_ = m / Sq, s = m % Sq, h = n / Dh, d = n % Dh;
                g_kh[(((long)(b_ * NHh + h)) * Sq + s) * Dh + d] = v;
            } else if (MODE == EP_VPROJT) {
                v += bias[n];
                int b_ = m / Sq, s = m % Sq, h = n / Dh, d = n % Dh;
                g_vhT[(((long)(b_ * NHh + h)) * Dh + d) * Sq + s] = v;
            } else if (MODE == EP_SCORES) {
                int b_ = g / NHh;
                long idx  = (long)g  * Sq * Sq + (long)m * Sq + n;
                long midx = (long)b_ * Sq * Sq + (long)m * Sq + n;
                v += attn_bias[idx];
                if (mask_true(mask, midx)) v = 0.f;
                g_xh[idx] = __float2half(v);
            } else if (MODE == EP_OGEMM) {
                int b_ = g / NHh, h = g % NHh;
                g_o[((long)(b_ * Sq + m)) * HIDN + h * Dh + n] = v;
            } else {  // EP_OUT
                v += bias[n];
                Cout[(long)m * N + n] = v;
            }
        }
    }
}

// ---------------------------------------------------------------------------
// Row softmax over g_y (GH*Sq rows of length Sq), in place
// ---------------------------------------------------------------------------
__global__ void softmax_rows_kernel() {
    float* p = g_y + (long)blockIdx.x * Sq;
    __shared__ float red[256];
    int t = threadIdx.x;

    float mx = -3.0e38f;
    for (int i = t; i < Sq; i += 256) mx = fmaxf(mx, p[i]);
    red[t] = mx; __syncthreads();
    for (int s = 128; s > 0; s >>= 1) {
        if (t < s) red[t] = fmaxf(red[t], red[t + s]);
        __syncthreads();
    }
    mx = red[0];
    __syncthreads();

    float sum = 0.f;
    for (int i = t; i < Sq; i += 256) {
        float e = expf(p[i] - mx);
        p[i] = e;
        sum += e;
    }
    red[t] = sum; __syncthreads();
    for (int s = 128; s > 0; s >>= 1) {
        if (t < s) red[t] += red[t + s];
        __syncthreads();
    }
    float inv = 1.f / red[0];
    for (int i = t; i < Sq; i += 256) p[i] *= inv;
}

// ---------------------------------------------------------------------------
extern "C" void kernel_launch(void* const* d_in, const int* in_sizes, int n_in,
                              void* d_out, int out_size)
{
    const float* q    = (const float*)d_in[0];
    const float* k    = (const float*)d_in[1];
    const float* v    = (const float*)d_in[2];
    const float* ab   = (const float*)d_in[3];
    const void*  mask = d_in[4];
    const float* w    = (const float*)d_in[5];
    const float* Wq   = (const float*)d_in[6];
    const float* bq   = (const float*)d_in[7];
    const float* Wk   = (const float*)d_in[8];
    const float* bk   = (const float*)d_in[9];
    const float* Wv   = (const float*)d_in[10];
    const float* bv   = (const float*)d_in[11];
    const float* Wo   = (const float*)d_in[12];
    const float* bo   = (const float*)d_in[13];
    float* out = (float*)d_out;

    detect_mask_kernel<<<1, 256>>>((const unsigned int*)mask, 65536);
    transpose_w_kernel<<<dim3(64, 64, Bsz), dim3(32, 8)>>>(w);

    const int M1 = Bsz * Sq;  // 4096
    sgemm_nt<EP_QPROJ><<<dim3(4, 32, 1), 256>>>(q, Wq, nullptr,
        M1, HIDN, HIDN, HIDN, HIDN, 0, 0, 1, bq, nullptr, nullptr);
    sgemm_nt<EP_KPROJ><<<dim3(4, 32, 1), 256>>>(k, Wk, nullptr,
        M1, HIDN, HIDN, HIDN, HIDN, 0, 0, 1, bk, nullptr, nullptr);
    sgemm_nt<EP_VPROJT><<<dim3(4, 32, 1), 256>>>(v, Wv, nullptr,
        M1, HIDN, HIDN, HIDN, HIDN, 0, 0, 1, bv, nullptr, nullptr);

    // Scores: per (b,h): [2048,64] @ [2048,64]^T + bias, masked -> g_xh (fp16)
    sgemm_nt<EP_SCORES><<<dim3(16, 16, GH), 256>>>(nullptr, nullptr, nullptr,
        Sq, Sq, Dh, Dh, Dh, (long)Sq * Dh, (long)Sq * Dh, 1,
        nullptr, ab, mask);

    // y = x @ w on HMMA tensor path (fp16 in, fp32 out)
    xw_mma_kernel<<<dim3(Sq/XBN, Sq/XBM, GH), 256>>>();

    softmax_rows_kernel<<<GH * Sq, 256>>>();

    // o = p @ vh: per (b,h): [2048,2048] @ [64,2048]^T
    sgemm_nt<EP_OGEMM><<<dim3(1, 16, GH), 256>>>(nullptr, nullptr, nullptr,
        Sq, Dh, Sq, Sq, Sq, (long)Sq * Sq, (long)Dh * Sq, 1,
        nullptr, nullptr, nullptr);

    // out = g_o @ Wo^T + bo
    sgemm_nt<EP_OUT><<<dim3(4, 32, 1), 256>>>(nullptr, Wo, out,
        M1, HIDN, HIDN, HIDN, HIDN, 0, 0, 1, bo, nullptr, nullptr);
}

// round 9
// speedup vs baseline: 6.2237x; 2.5633x over previous
#include <cuda_runtime.h>
#include <cuda_fp16.h>
#include <cstdint>

// Problem constants
#define Bsz 2
#define Sq  2048
#define HIDN 512
#define NHh 8
#define Dh  64
#define GH  (Bsz*NHh)

// ---------------------------------------------------------------------------
// Scratch (__device__ globals; allocation-free rule)
// ---------------------------------------------------------------------------
__device__ __align__(128) __half g_q16 [Bsz*Sq*HIDN];   // fp16 inputs
__device__ __align__(128) __half g_k16 [Bsz*Sq*HIDN];
__device__ __align__(128) __half g_v16h[Bsz*Sq*HIDN];   // v split
__device__ __align__(128) __half g_v16l[Bsz*Sq*HIDN];
__device__ __align__(128) __half g_Wq16[HIDN*HIDN];
__device__ __align__(128) __half g_Wk16[HIDN*HIDN];
__device__ __align__(128) __half g_Wvh [HIDN*HIDN];     // Wv split
__device__ __align__(128) __half g_Wvl [HIDN*HIDN];
__device__ __align__(128) __half g_Woh [HIDN*HIDN];     // Wo split
__device__ __align__(128) __half g_Wol [HIDN*HIDN];

__device__ __align__(128) __half g_qh [GH*Sq*Dh];       // [g][s][d] scaled
__device__ __align__(128) __half g_kh [GH*Sq*Dh];       // [g][s][d]
__device__ __align__(128) __half g_vh [GH*Dh*Sq];       // [g][d][s] split
__device__ __align__(128) __half g_vl [GH*Dh*Sq];
__device__ __align__(128) __half g_xh [(long)GH*Sq*Sq]; // scores fp16
__device__ __align__(128) __half g_wTh[(long)Bsz*Sq*Sq];// w^T fp16
__device__ __align__(128) float  g_y  [(long)GH*Sq*Sq]; // logits fp32
__device__ __align__(128) __half g_ph [(long)GH*Sq*Sq]; // softmax split
__device__ __align__(128) __half g_pl [(long)GH*Sq*Sq];
__device__ __align__(128) __half g_oh [Bsz*Sq*HIDN];    // o split [b][s][hd]
__device__ __align__(128) __half g_ol [Bsz*Sq*HIDN];
__device__ int g_mask_mode;

// ---------------------------------------------------------------------------
// Mask dtype sniffer
// ---------------------------------------------------------------------------
__global__ void detect_mask_kernel(const unsigned int* __restrict__ m, int nwords) {
    __shared__ int s_multi;
    if (threadIdx.x == 0) s_multi = 0;
    __syncthreads();
    int found = 0;
    for (int i = threadIdx.x; i < nwords; i += blockDim.x) {
        unsigned int v = m[i];
        if (v > 1u && v != 0x3F800000u) found = 1;
    }
    if (found) atomicOr(&s_multi, 1);
    __syncthreads();
    if (threadIdx.x == 0) g_mask_mode = s_multi ? 2 : 0;
}
__device__ __forceinline__ bool mask_true(const void* mask, long idx) {
    if (g_mask_mode == 2) return ((const unsigned char*)mask)[idx] != 0;
    return ((const unsigned int*)mask)[idx] != 0u;
}

// ---------------------------------------------------------------------------
// Conversions — destinations are template-selected device globals so that
// kernel_launch never needs cudaGetSymbolAddress (pure-launch capture path).
// ---------------------------------------------------------------------------
enum { C_Q = 0, C_K, C_WQ, C_WK };
enum { S_V = 0, S_WV, S_WO };

template <int WHICH>
__global__ void conv_half_t(const float* __restrict__ s, int n) {
    __half* d = (WHICH == C_Q)  ? g_q16 :
                (WHICH == C_K)  ? g_k16 :
                (WHICH == C_WQ) ? g_Wq16 : g_Wk16;
    int i = blockIdx.x * blockDim.x + threadIdx.x;
    if (i < n) d[i] = __float2half(s[i]);
}

template <int WHICH>
__global__ void conv_split_t(const float* __restrict__ s, int n) {
    __half* h = (WHICH == S_V) ? g_v16h : (WHICH == S_WV) ? g_Wvh : g_Woh;
    __half* l = (WHICH == S_V) ? g_v16l : (WHICH == S_WV) ? g_Wvl : g_Wol;
    int i = blockIdx.x * blockDim.x + threadIdx.x;
    if (i < n) {
        float v = s[i];
        __half a = __float2half(v);
        h[i] = a;
        l[i] = __float2half(v - __half2float(a));
    }
}

// w transpose -> fp16
__global__ void transpose_w_kernel(const float* __restrict__ w) {
    __shared__ float t[32][33];
    int b = blockIdx.z;
    int k0 = blockIdx.y * 32, l0 = blockIdx.x * 32;
    const float* wb = w + (long)b * Sq * Sq;
    __half* ob = g_wTh + (long)b * Sq * Sq;
    int x = threadIdx.x, y = threadIdx.y;
    #pragma unroll
    for (int i = 0; i < 32; i += 8)
        t[y + i][x] = wb[(long)(k0 + y + i) * Sq + (l0 + x)];
    __syncthreads();
    #pragma unroll
    for (int i = 0; i < 32; i += 8)
        ob[(long)(l0 + y + i) * Sq + (k0 + x)] = __float2half(t[x][y + i]);
}

// ---------------------------------------------------------------------------
// HMMA primitives
// ---------------------------------------------------------------------------
static __device__ __forceinline__ uint32_t sw64(uint32_t x) { return x ^ ((x >> 3) & 0x30); }

__device__ __forceinline__ void cp_async16(uint32_t saddr, const void* gaddr) {
    asm volatile("cp.async.cg.shared.global [%0], [%1], 16;"
                 :: "r"(saddr), "l"(gaddr) : "memory");
}
__device__ __forceinline__ void ldsm_x4(uint32_t* r, uint32_t addr) {
    asm volatile("ldmatrix.sync.aligned.m8n8.x4.shared.b16 {%0,%1,%2,%3}, [%4];"
                 : "=r"(r[0]), "=r"(r[1]), "=r"(r[2]), "=r"(r[3]) : "r"(addr));
}
__device__ __forceinline__ void mma16816(float* c, const uint32_t* a, const uint32_t* b) {
    asm volatile(
        "mma.sync.aligned.m16n8k16.row.col.f32.f16.f16.f32 "
        "{%0,%1,%2,%3}, {%4,%5,%6,%7}, {%8,%9}, {%0,%1,%2,%3};"
        : "+f"(c[0]), "+f"(c[1]), "+f"(c[2]), "+f"(c[3])
        : "r"(a[0]), "r"(a[1]), "r"(a[2]), "r"(a[3]), "r"(b[0]), "r"(b[1]));
}

// ---------------------------------------------------------------------------
// Unified HMMA GEMM template.  NT: C[m,n] = sum_seg sum_k A[m,k]*B[n,k].
// 128 threads, 2x2 warps.  3-stage cp.async, SW64, k-tile 32.
// ---------------------------------------------------------------------------
enum { M_QPROJ = 0, M_KPROJ, M_VPROJ, M_SCORES, M_XW, M_OGEMM, M_OUT };

template <int BM, int BN, int MODE>
__global__ void __launch_bounds__(128)
hgemm(const float* __restrict__ bias, const float* __restrict__ attn_bias,
      const void* __restrict__ mask, float* __restrict__ Cext)
{
    constexpr int KD   = (MODE == M_SCORES) ? 64 :
                         (MODE == M_XW || MODE == M_OGEMM) ? 2048 : 512;
    constexpr int NSEG = (MODE == M_VPROJ || MODE == M_OGEMM || MODE == M_OUT) ? 3 : 1;
    constexpr int TPS  = KD / 32;
    constexpr int TOT  = NSEG * TPS;
    constexpr int ROWS = BM + BN;
    constexpr int STAGE = ROWS * 64;
    constexpr int TMF = BM / 2 / 16;   // m-frags per warp (warp tile BM/2)
    constexpr int TNF = BN / 2 / 8;    // n-frags per warp (warp tile BN/2)

    __shared__ __align__(1024) char smem[3 * STAGE];
    uint32_t sbase = (uint32_t)__cvta_generic_to_shared(smem);

    int tid = threadIdx.x;
    int wid = tid >> 5, lane = tid & 31;
    int wm = (wid >> 1) * (BM / 2);
    int wn = (wid & 1) * (BN / 2);

    int g  = blockIdx.z;
    int m0 = blockIdx.y * BM;
    int n0 = blockIdx.x * BN;

    // segment base pointers (already offset by m0/n0)
    const __half *A0, *A1 = nullptr, *A2 = nullptr;
    const __half *B0, *B1 = nullptr, *B2 = nullptr;
    if (MODE == M_QPROJ)      { A0 = g_q16;  B0 = g_Wq16; }
    else if (MODE == M_KPROJ) { A0 = g_k16;  B0 = g_Wk16; }
    else if (MODE == M_VPROJ) { A0 = g_v16h; A1 = g_v16h; A2 = g_v16l;
                                B0 = g_Wvh;  B1 = g_Wvl;  B2 = g_Wvh; }
    else if (MODE == M_SCORES){ A0 = g_qh + (long)g * Sq * Dh;
                                B0 = g_kh + (long)g * Sq * Dh; }
    else if (MODE == M_XW)    { A0 = g_xh  + (long)g        * Sq * Sq;
                                B0 = g_wTh + (long)(g >> 3) * Sq * Sq; }
    else if (MODE == M_OGEMM) { long ao = (long)g * Sq * Sq;
                                long bo = (long)g * Dh * Sq;
                                A0 = g_ph + ao; A1 = g_ph + ao; A2 = g_pl + ao;
                                B0 = g_vh + bo; B1 = g_vl + bo; B2 = g_vh + bo; }
    else                      { A0 = g_oh;  A1 = g_oh; A2 = g_ol;
                                B0 = g_Woh; B1 = g_Wol; B2 = g_Woh; }
    A0 += (long)m0 * KD; if (NSEG == 3) { A1 += (long)m0 * KD; A2 += (long)m0 * KD; }
    B0 += (long)n0 * KD; if (NSEG == 3) { B1 += (long)n0 * KD; B2 += (long)n0 * KD; }

    float c[TMF][TNF][4];
    #pragma unroll
    for (int t = 0; t < TMF; t++)
        #pragma unroll
        for (int u = 0; u < TNF; u++)
            #pragma unroll
            for (int i = 0; i < 4; i++) c[t][u][i] = 0.f;

    auto load_stage = [&](int st, int kt) {
        int seg = kt / TPS, kk = kt % TPS;
        const __half* Ak = (NSEG == 1 || seg == 0) ? A0 : (seg == 1) ? A1 : A2;
        const __half* Bk = (NSEG == 1 || seg == 0) ? B0 : (seg == 1) ? B1 : B2;
        Ak += kk * 32; Bk += kk * 32;
        uint32_t base = sbase + st * STAGE;
        #pragma unroll
        for (int t = tid; t < ROWS * 4; t += 128) {
            int r = t >> 2, ch = t & 3;
            if (r < BM)
                cp_async16(base + sw64(r * 64 + ch * 16),
                           Ak + (long)r * KD + ch * 8);
            else {
                int rb = r - BM;
                cp_async16(base + BM * 64 + sw64(rb * 64 + ch * 16),
                           Bk + (long)rb * KD + ch * 8);
            }
        }
    };

    load_stage(0, 0);
    asm volatile("cp.async.commit_group;" ::: "memory");
    if (TOT > 1) load_stage(1, 1);
    asm volatile("cp.async.commit_group;" ::: "memory");

    for (int kt = 0; kt < TOT; kt++) {
        int st = kt % 3;
        asm volatile("cp.async.wait_group 1;" ::: "memory");
        __syncthreads();

        int kn = kt + 2;
        if (kn < TOT) load_stage(kn % 3, kn);
        asm volatile("cp.async.commit_group;" ::: "memory");

        uint32_t abase = sbase + st * STAGE;
        uint32_t bbase = abase + BM * 64;
        #pragma unroll
        for (int ks = 0; ks < 2; ks++) {
            uint32_t a[TMF][4], b[TNF][2];
            #pragma unroll
            for (int t = 0; t < TMF; t++) {
                int row = wm + t * 16 + (lane & 15);
                ldsm_x4(a[t], abase + sw64(row * 64 + ks * 32 + (lane >> 4) * 16));
            }
            #pragma unroll
            for (int u = 0; u < TNF; u += 2) {
                int grp = lane >> 3;
                int row = wn + u * 8 + (grp >> 1) * 8 + (lane & 7);
                int kb  = (grp & 1) * 16;
                uint32_t rr[4];
                ldsm_x4(rr, bbase + sw64(row * 64 + ks * 32 + kb));
                b[u][0] = rr[0]; b[u][1] = rr[1];
                b[u + 1][0] = rr[2]; b[u + 1][1] = rr[3];
            }
            #pragma unroll
            for (int t = 0; t < TMF; t++)
                #pragma unroll
                for (int u = 0; u < TNF; u++)
                    mma16816(c[t][u], a[t], b[u]);
        }
    }

    // ---------------- epilogue ----------------
    auto store = [&](int m, int n, float v) {
        if (MODE == M_QPROJ) {
            float val = (v + bias[n]) * 0.125f;
            int b_ = m >> 11, s = m & 2047, h = n >> 6, d = n & 63;
            g_qh[((long)((b_ * NHh + h) * Sq + s)) * Dh + d] = __float2half(val);
        } else if (MODE == M_KPROJ) {
            float val = v + bias[n];
            int b_ = m >> 11, s = m & 2047, h = n >> 6, d = n & 63;
            g_kh[((long)((b_ * NHh + h) * Sq + s)) * Dh + d] = __float2half(val);
        } else if (MODE == M_VPROJ) {
            float val = v + bias[n];
            int b_ = m >> 11, s = m & 2047, h = n >> 6, d = n & 63;
            long idx = ((long)((b_ * NHh + h) * Dh + d)) * Sq + s;
            __half hh = __float2half(val);
            g_vh[idx] = hh;
            g_vl[idx] = __float2half(val - __half2float(hh));
        } else if (MODE == M_SCORES) {
            long idx  = (long)g * Sq * Sq + (long)m * Sq + n;
            long midx = (long)(g >> 3) * Sq * Sq + (long)m * Sq + n;
            float val = v + attn_bias[idx];
            if (mask_true(mask, midx)) val = 0.f;
            g_xh[idx] = __float2half(val);
        } else if (MODE == M_XW) {
            g_y[(long)g * Sq * Sq + (long)m * Sq + n] = v;
        } else if (MODE == M_OGEMM) {
            int b_ = g >> 3, h = g & 7;
            long idx = ((long)(b_ * Sq + m)) * HIDN + h * Dh + n;
            __half hh = __float2half(v);
            g_oh[idx] = hh;
            g_ol[idx] = __float2half(v - __half2float(hh));
        } else {  // M_OUT
            Cext[(long)m * HIDN + n] = v + bias[n];
        }
    };

    #pragma unroll
    for (int t = 0; t < TMF; t++) {
        int m = m0 + wm + t * 16 + (lane >> 2);
        #pragma unroll
        for (int u = 0; u < TNF; u++) {
            int n = n0 + wn + u * 8 + (lane & 3) * 2;
            store(m,     n,     c[t][u][0]);
            store(m,     n + 1, c[t][u][1]);
            store(m + 8, n,     c[t][u][2]);
            store(m + 8, n + 1, c[t][u][3]);
        }
    }
}

// ---------------------------------------------------------------------------
// Fused single-read softmax: g_y row (fp32) -> (ph, pl) fp16 split
// ---------------------------------------------------------------------------
__global__ void __launch_bounds__(256) softmax_kernel() {
    long row = blockIdx.x;
    const float* p = g_y + row * Sq;
    __half* oh = g_ph + row * Sq;
    __half* ol = g_pl + row * Sq;
    __shared__ float buf[Sq];
    __shared__ float red[256];
    int t = threadIdx.x;

    float mx = -3.0e38f;
    #pragma unroll
    for (int i = 0; i < Sq / 1024; i++) {
        float4 v = ((const float4*)p)[t + i * 256];
        ((float4*)buf)[t + i * 256] = v;
        mx = fmaxf(mx, fmaxf(fmaxf(v.x, v.y), fmaxf(v.z, v.w)));
    }
    red[t] = mx; __syncthreads();
    for (int s = 128; s > 0; s >>= 1) {
        if (t < s) red[t] = fmaxf(red[t], red[t + s]);
        __syncthreads();
    }
    mx = red[0];
    __syncthreads();

    float sum = 0.f;
    #pragma unroll
    for (int i = 0; i < Sq / 256; i++) {
        float e = expf(buf[t + i * 256] - mx);
        buf[t + i * 256] = e;
        sum += e;
    }
    red[t] = sum; __syncthreads();
    for (int s = 128; s > 0; s >>= 1) {
        if (t < s) red[t] += red[t + s];
        __syncthreads();
    }
    float inv = 1.f / red[0];
    __syncthreads();

    #pragma unroll
    for (int i = 0; i < Sq / 256; i++) {
        float pv = buf[t + i * 256] * inv;
        __half hh = __float2half(pv);
        oh[t + i * 256] = hh;
        ol[t + i * 256] = __float2half(pv - __half2float(hh));
    }
}

// ---------------------------------------------------------------------------
extern "C" void kernel_launch(void* const* d_in, const int* in_sizes, int n_in,
                              void* d_out, int out_size)
{
    const float* q    = (const float*)d_in[0];
    const float* k    = (const float*)d_in[1];
    const float* v    = (const float*)d_in[2];
    const float* ab   = (const float*)d_in[3];
    const void*  mask = d_in[4];
    const float* w    = (const float*)d_in[5];
    const float* Wq   = (const float*)d_in[6];
    const float* bq   = (const float*)d_in[7];
    const float* Wk   = (const float*)d_in[8];
    const float* bk   = (const float*)d_in[9];
    const float* Wv   = (const float*)d_in[10];
    const float* bv   = (const float*)d_in[11];
    const float* Wo   = (const float*)d_in[12];
    const float* bo   = (const float*)d_in[13];
    float* out = (float*)d_out;

    const int NIN = Bsz * Sq * HIDN;      // 2M
    const int NW  = HIDN * HIDN;          // 256K

    detect_mask_kernel<<<1, 256>>>((const unsigned int*)mask, 65536);

    conv_half_t<C_Q> <<<(NIN + 511) / 512, 512>>>(q, NIN);
    conv_half_t<C_K> <<<(NIN + 511) / 512, 512>>>(k, NIN);
    conv_split_t<S_V><<<(NIN + 511) / 512, 512>>>(v, NIN);
    conv_half_t<C_WQ><<<(NW  + 511) / 512, 512>>>(Wq, NW);
    conv_half_t<C_WK><<<(NW  + 511) / 512, 512>>>(Wk, NW);
    conv_split_t<S_WV><<<(NW + 511) / 512, 512>>>(Wv, NW);
    conv_split_t<S_WO><<<(NW + 511) / 512, 512>>>(Wo, NW);

    transpose_w_kernel<<<dim3(64, 64, Bsz), dim3(32, 8)>>>(w);

    // Projections: [4096,512] @ [512,512]^T
    hgemm<128, 128, M_QPROJ><<<dim3(4, 32, 1), 128>>>(bq, nullptr, nullptr, nullptr);
    hgemm<128, 128, M_KPROJ><<<dim3(4, 32, 1), 128>>>(bk, nullptr, nullptr, nullptr);
    hgemm<128, 128, M_VPROJ><<<dim3(4, 32, 1), 128>>>(bv, nullptr, nullptr, nullptr);

    // Scores: [2048,64]@[2048,64]^T + bias, mask -> g_xh
    hgemm<128, 128, M_SCORES><<<dim3(16, 16, GH), 128>>>(nullptr, ab, mask, nullptr);

    // y = x @ w (dominant)
    hgemm<128, 128, M_XW><<<dim3(16, 16, GH), 128>>>(nullptr, nullptr, nullptr, nullptr);

    softmax_kernel<<<GH * Sq, 256>>>();

    // o = p @ v^T  (split 3-pass): [2048,2048]@[64,2048]^T
    hgemm<128, 64, M_OGEMM><<<dim3(1, 16, GH), 128>>>(nullptr, nullptr, nullptr, nullptr);

    // out = o @ Wo^T + bo (split 3-pass)
    hgemm<128, 128, M_OUT><<<dim3(4, 32, 1), 128>>>(bo, nullptr, nullptr, out);
}

// round 10
// speedup vs baseline: 6.6189x; 1.0635x over previous
#include <cuda_runtime.h>
#include <cuda_fp16.h>
#include <cstdint>

// Problem constants
#define Bsz 2
#define Sq  2048
#define HIDN 512
#define NHh 8
#define Dh  64
#define GH  (Bsz*NHh)

// ---------------------------------------------------------------------------
// Scratch (__device__ globals; allocation-free rule)
// ---------------------------------------------------------------------------
__device__ __align__(128) __half g_q16 [Bsz*Sq*HIDN];   // fp16 inputs
__device__ __align__(128) __half g_k16 [Bsz*Sq*HIDN];
__device__ __align__(128) __half g_v16h[Bsz*Sq*HIDN];   // v split
__device__ __align__(128) __half g_v16l[Bsz*Sq*HIDN];
__device__ __align__(128) __half g_Wq16[HIDN*HIDN];
__device__ __align__(128) __half g_Wk16[HIDN*HIDN];
__device__ __align__(128) __half g_Wvh [HIDN*HIDN];     // Wv split
__device__ __align__(128) __half g_Wvl [HIDN*HIDN];
__device__ __align__(128) __half g_Woh [HIDN*HIDN];     // Wo split
__device__ __align__(128) __half g_Wol [HIDN*HIDN];

__device__ __align__(128) __half g_qh [GH*Sq*Dh];       // [g][s][d] scaled
__device__ __align__(128) __half g_kh [GH*Sq*Dh];       // [g][s][d]
__device__ __align__(128) __half g_vh [GH*Dh*Sq];       // [g][d][s] split
__device__ __align__(128) __half g_vl [GH*Dh*Sq];
__device__ __align__(128) __half g_xh [(long)GH*Sq*Sq]; // scores fp16
__device__ __align__(128) __half g_wTh[(long)Bsz*Sq*Sq];// w^T fp16
__device__ __align__(128) float  g_y  [(long)GH*Sq*Sq]; // logits fp32
__device__ __align__(128) __half g_ph [(long)GH*Sq*Sq]; // softmax split
__device__ __align__(128) __half g_pl [(long)GH*Sq*Sq];
__device__ __align__(128) __half g_oh [Bsz*Sq*HIDN];    // o split [b][s][hd]
__device__ __align__(128) __half g_ol [Bsz*Sq*HIDN];
__device__ int g_mask_mode;

// ---------------------------------------------------------------------------
// Mask dtype sniffer
// ---------------------------------------------------------------------------
__global__ void detect_mask_kernel(const unsigned int* __restrict__ m, int nwords) {
    __shared__ int s_multi;
    if (threadIdx.x == 0) s_multi = 0;
    __syncthreads();
    int found = 0;
    for (int i = threadIdx.x; i < nwords; i += blockDim.x) {
        unsigned int v = m[i];
        if (v > 1u && v != 0x3F800000u) found = 1;
    }
    if (found) atomicOr(&s_multi, 1);
    __syncthreads();
    if (threadIdx.x == 0) g_mask_mode = s_multi ? 2 : 0;
}
__device__ __forceinline__ bool mask_true(const void* mask, long idx) {
    if (g_mask_mode == 2) return ((const unsigned char*)mask)[idx] != 0;
    return ((const unsigned int*)mask)[idx] != 0u;
}

// ---------------------------------------------------------------------------
// Conversions (vectorized: float4 in, half2 out; n always divisible by 4)
// ---------------------------------------------------------------------------
enum { C_Q = 0, C_K, C_WQ, C_WK };
enum { S_V = 0, S_WV, S_WO };

template <int WHICH>
__global__ void conv_half_t(const float* __restrict__ s, int n) {
    __half* d = (WHICH == C_Q)  ? g_q16 :
                (WHICH == C_K)  ? g_k16 :
                (WHICH == C_WQ) ? g_Wq16 : g_Wk16;
    int i = (blockIdx.x * blockDim.x + threadIdx.x) * 4;
    if (i < n) {
        float4 v = *(const float4*)(s + i);
        ((__half2*)(d + i))[0] = __floats2half2_rn(v.x, v.y);
        ((__half2*)(d + i))[1] = __floats2half2_rn(v.z, v.w);
    }
}

template <int WHICH>
__global__ void conv_split_t(const float* __restrict__ s, int n) {
    __half* h = (WHICH == S_V) ? g_v16h : (WHICH == S_WV) ? g_Wvh : g_Woh;
    __half* l = (WHICH == S_V) ? g_v16l : (WHICH == S_WV) ? g_Wvl : g_Wol;
    int i = (blockIdx.x * blockDim.x + threadIdx.x) * 4;
    if (i < n) {
        float4 v = *(const float4*)(s + i);
        float f[4] = {v.x, v.y, v.z, v.w};
        __half hh[4], ll[4];
        #pragma unroll
        for (int j = 0; j < 4; j++) {
            hh[j] = __float2half(f[j]);
            ll[j] = __float2half(f[j] - __half2float(hh[j]));
        }
        *(uint2*)(h + i) = *(uint2*)hh;
        *(uint2*)(l + i) = *(uint2*)ll;
    }
}

// w transpose -> fp16
__global__ void transpose_w_kernel(const float* __restrict__ w) {
    __shared__ float t[32][33];
    int b = blockIdx.z;
    int k0 = blockIdx.y * 32, l0 = blockIdx.x * 32;
    const float* wb = w + (long)b * Sq * Sq;
    __half* ob = g_wTh + (long)b * Sq * Sq;
    int x = threadIdx.x, y = threadIdx.y;
    #pragma unroll
    for (int i = 0; i < 32; i += 8)
        t[y + i][x] = wb[(long)(k0 + y + i) * Sq + (l0 + x)];
    __syncthreads();
    #pragma unroll
    for (int i = 0; i < 32; i += 8)
        ob[(long)(l0 + y + i) * Sq + (k0 + x)] = __float2half(t[x][y + i]);
}

// ---------------------------------------------------------------------------
// HMMA primitives
// ---------------------------------------------------------------------------
static __device__ __forceinline__ uint32_t sw64 (uint32_t x) { return x ^ ((x >> 3) & 0x30); }
static __device__ __forceinline__ uint32_t sw128(uint32_t x) { return x ^ ((x >> 3) & 0x70); }

__device__ __forceinline__ void cp_async16(uint32_t saddr, const void* gaddr) {
    asm volatile("cp.async.cg.shared.global [%0], [%1], 16;"
                 :: "r"(saddr), "l"(gaddr) : "memory");
}
__device__ __forceinline__ void ldsm_x4(uint32_t* r, uint32_t addr) {
    asm volatile("ldmatrix.sync.aligned.m8n8.x4.shared.b16 {%0,%1,%2,%3}, [%4];"
                 : "=r"(r[0]), "=r"(r[1]), "=r"(r[2]), "=r"(r[3]) : "r"(addr));
}
__device__ __forceinline__ void mma16816(float* c, const uint32_t* a, const uint32_t* b) {
    asm volatile(
        "mma.sync.aligned.m16n8k16.row.col.f32.f16.f16.f32 "
        "{%0,%1,%2,%3}, {%4,%5,%6,%7}, {%8,%9}, {%0,%1,%2,%3};"
        : "+f"(c[0]), "+f"(c[1]), "+f"(c[2]), "+f"(c[3])
        : "r"(a[0]), "r"(a[1]), "r"(a[2]), "r"(a[3]), "r"(b[0]), "r"(b[1]));
}

// ===========================================================================
// XW v2: y = x @ w^T per head.  128 threads, BM=BN=128 (warp tile 64x64),
// k-tile 64 (128B SW128 rows), 3-stage dynamic-smem cp.async pipeline,
// register double-buffered fragments.
// ===========================================================================
#define X2STAGE 32768                    // (128+128) rows * 128B
#define X2SMEM  (3*X2STAGE)              // 96 KB dynamic

__global__ void __launch_bounds__(128) xw2_kernel() {
    extern __shared__ __align__(1024) char smem2[];
    uint32_t sbase = (uint32_t)__cvta_generic_to_shared(smem2);

    int tid = threadIdx.x;
    int wid = tid >> 5, lane = tid & 31;
    int wm = (wid >> 1) * 64;
    int wn = (wid & 1) * 64;

    int g  = blockIdx.z;
    int m0 = blockIdx.y * 128;
    int n0 = blockIdx.x * 128;
    const __half* Ag = g_xh  + (long)g        * Sq * Sq + (long)m0 * Sq;
    const __half* Bg = g_wTh + (long)(g >> 3) * Sq * Sq + (long)n0 * Sq;

    float c[4][8][4];
    #pragma unroll
    for (int t = 0; t < 4; t++)
        #pragma unroll
        for (int u = 0; u < 8; u++)
            #pragma unroll
            for (int i = 0; i < 4; i++) c[t][u][i] = 0.f;

    // stage loader: 256 rows x 128B (A rows 0-127, B rows 128-255), SW128
    auto load_stage = [&](int st, int kt) {
        uint32_t base = sbase + st * X2STAGE;
        const __half* Ak = Ag + kt * 64;
        const __half* Bk = Bg + kt * 64;
        #pragma unroll
        for (int it = 0; it < 16; it++) {
            int t = tid + it * 128;            // 0..2047
            int r = t >> 3, ch = t & 7;
            if (r < 128)
                cp_async16(base + sw128(r * 128 + ch * 16),
                           Ak + (long)r * Sq + ch * 8);
            else {
                int rb = r - 128;
                cp_async16(base + 16384 + sw128(rb * 128 + ch * 16),
                           Bk + (long)rb * Sq + ch * 8);
            }
        }
    };

    load_stage(0, 0);
    asm volatile("cp.async.commit_group;" ::: "memory");
    load_stage(1, 1);
    asm volatile("cp.async.commit_group;" ::: "memory");

    uint32_t a[2][4][4], b[2][8][2];

    for (int kt = 0; kt < 32; kt++) {       // K=2048, tile 64
        int st = kt % 3;
        asm volatile("cp.async.wait_group 1;" ::: "memory");
        __syncthreads();

        int kn = kt + 2;
        if (kn < 32) load_stage(kn % 3, kn);
        asm volatile("cp.async.commit_group;" ::: "memory");

        uint32_t abase = sbase + st * X2STAGE;
        uint32_t bbase = abase + 16384;

        auto load_a = [&](int buf, int ks) {
            #pragma unroll
            for (int t = 0; t < 4; t++) {
                int row = wm + t * 16 + (lane & 15);
                ldsm_x4(a[buf][t], abase + sw128(row * 128 + ks * 32 + (lane >> 4) * 16));
            }
        };
        auto load_b = [&](int buf, int ks) {
            #pragma unroll
            for (int u = 0; u < 8; u += 2) {
                int grp = lane >> 3;
                int row = wn + u * 8 + (grp >> 1) * 8 + (lane & 7);
                int kb  = (grp & 1) * 16;
                uint32_t rr[4];
                ldsm_x4(rr, bbase + sw128(row * 128 + ks * 32 + kb));
                b[buf][u][0] = rr[0];     b[buf][u][1] = rr[1];
                b[buf][u + 1][0] = rr[2]; b[buf][u + 1][1] = rr[3];
            }
        };

        load_a(0, 0);
        load_b(0, 0);
        #pragma unroll
        for (int ks = 0; ks < 4; ks++) {    // 4 x k16 per tile
            int cur = ks & 1, nxt = cur ^ 1;
            if (ks < 3) { load_a(nxt, ks + 1); load_b(nxt, ks + 1); }
            #pragma unroll
            for (int t = 0; t < 4; t++)
                #pragma unroll
                for (int u = 0; u < 8; u++)
                    mma16816(c[t][u], a[cur][t], b[cur][u]);
        }
    }

    // epilogue -> g_y fp32
    float* Cg = g_y + (long)g * Sq * Sq;
    #pragma unroll
    for (int t = 0; t < 4; t++) {
        int m = m0 + wm + t * 16 + (lane >> 2);
        #pragma unroll
        for (int u = 0; u < 8; u++) {
            int n = n0 + wn + u * 8 + (lane & 3) * 2;
            float* p = Cg + (long)m * Sq + n;
            p[0] = c[t][u][0]; p[1] = c[t][u][1];
            p[8 * Sq] = c[t][u][2]; p[8 * Sq + 1] = c[t][u][3];
        }
    }
}

// ---------------------------------------------------------------------------
// Unified HMMA GEMM template (small stages).  NT: C = sum_seg A B^T.
// 128 threads, 2x2 warps.  3-stage cp.async, SW64, k-tile 32.
// ---------------------------------------------------------------------------
enum { M_QPROJ = 0, M_KPROJ, M_VPROJ, M_SCORES, M_OGEMM, M_OUT };

template <int BM, int BN, int MODE>
__global__ void __launch_bounds__(128)
hgemm(const float* __restrict__ bias, const float* __restrict__ attn_bias,
      const void* __restrict__ mask, float* __restrict__ Cext)
{
    constexpr int KD   = (MODE == M_SCORES) ? 64 :
                         (MODE == M_OGEMM) ? 2048 : 512;
    constexpr int NSEG = (MODE == M_VPROJ || MODE == M_OGEMM || MODE == M_OUT) ? 3 : 1;
    constexpr int TPS  = KD / 32;
    constexpr int TOT  = NSEG * TPS;
    constexpr int ROWS = BM + BN;
    constexpr int STAGE = ROWS * 64;
    constexpr int TMF = BM / 2 / 16;
    constexpr int TNF = BN / 2 / 8;

    __shared__ __align__(1024) char smem[3 * STAGE];
    uint32_t sbase = (uint32_t)__cvta_generic_to_shared(smem);

    int tid = threadIdx.x;
    int wid = tid >> 5, lane = tid & 31;
    int wm = (wid >> 1) * (BM / 2);
    int wn = (wid & 1) * (BN / 2);

    int g  = blockIdx.z;
    int m0 = blockIdx.y * BM;
    int n0 = blockIdx.x * BN;

    const __half *A0, *A1 = nullptr, *A2 = nullptr;
    const __half *B0, *B1 = nullptr, *B2 = nullptr;
    if (MODE == M_QPROJ)      { A0 = g_q16;  B0 = g_Wq16; }
    else if (MODE == M_KPROJ) { A0 = g_k16;  B0 = g_Wk16; }
    else if (MODE == M_VPROJ) { A0 = g_v16h; A1 = g_v16h; A2 = g_v16l;
                                B0 = g_Wvh;  B1 = g_Wvl;  B2 = g_Wvh; }
    else if (MODE == M_SCORES){ A0 = g_qh + (long)g * Sq * Dh;
                                B0 = g_kh + (long)g * Sq * Dh; }
    else if (MODE == M_OGEMM) { long ao = (long)g * Sq * Sq;
                                long bo = (long)g * Dh * Sq;
                                A0 = g_ph + ao; A1 = g_ph + ao; A2 = g_pl + ao;
                                B0 = g_vh + bo; B1 = g_vl + bo; B2 = g_vh + bo; }
    else                      { A0 = g_oh;  A1 = g_oh; A2 = g_ol;
                                B0 = g_Woh; B1 = g_Wol; B2 = g_Woh; }
    A0 += (long)m0 * KD; if (NSEG == 3) { A1 += (long)m0 * KD; A2 += (long)m0 * KD; }
    B0 += (long)n0 * KD; if (NSEG == 3) { B1 += (long)n0 * KD; B2 += (long)n0 * KD; }

    float c[TMF][TNF][4];
    #pragma unroll
    for (int t = 0; t < TMF; t++)
        #pragma unroll
        for (int u = 0; u < TNF; u++)
            #pragma unroll
            for (int i = 0; i < 4; i++) c[t][u][i] = 0.f;

    auto load_stage = [&](int st, int kt) {
        int seg = kt / TPS, kk = kt % TPS;
        const __half* Ak = (NSEG == 1 || seg == 0) ? A0 : (seg == 1) ? A1 : A2;
        const __half* Bk = (NSEG == 1 || seg == 0) ? B0 : (seg == 1) ? B1 : B2;
        Ak += kk * 32; Bk += kk * 32;
        uint32_t base = sbase + st * STAGE;
        #pragma unroll
        for (int t = tid; t < ROWS * 4; t += 128) {
            int r = t >> 2, ch = t & 3;
            if (r < BM)
                cp_async16(base + sw64(r * 64 + ch * 16),
                           Ak + (long)r * KD + ch * 8);
            else {
                int rb = r - BM;
                cp_async16(base + BM * 64 + sw64(rb * 64 + ch * 16),
                           Bk + (long)rb * KD + ch * 8);
            }
        }
    };

    load_stage(0, 0);
    asm volatile("cp.async.commit_group;" ::: "memory");
    if (TOT > 1) load_stage(1, 1);
    asm volatile("cp.async.commit_group;" ::: "memory");

    for (int kt = 0; kt < TOT; kt++) {
        int st = kt % 3;
        asm volatile("cp.async.wait_group 1;" ::: "memory");
        __syncthreads();

        int kn = kt + 2;
        if (kn < TOT) load_stage(kn % 3, kn);
        asm volatile("cp.async.commit_group;" ::: "memory");

        uint32_t abase = sbase + st * STAGE;
        uint32_t bbase = abase + BM * 64;
        #pragma unroll
        for (int ks = 0; ks < 2; ks++) {
            uint32_t a[TMF][4], b[TNF][2];
            #pragma unroll
            for (int t = 0; t < TMF; t++) {
                int row = wm + t * 16 + (lane & 15);
                ldsm_x4(a[t], abase + sw64(row * 64 + ks * 32 + (lane >> 4) * 16));
            }
            #pragma unroll
            for (int u = 0; u < TNF; u += 2) {
                int grp = lane >> 3;
                int row = wn + u * 8 + (grp >> 1) * 8 + (lane & 7);
                int kb  = (grp & 1) * 16;
                uint32_t rr[4];
                ldsm_x4(rr, bbase + sw64(row * 64 + ks * 32 + kb));
                b[u][0] = rr[0]; b[u][1] = rr[1];
                b[u + 1][0] = rr[2]; b[u + 1][1] = rr[3];
            }
            #pragma unroll
            for (int t = 0; t < TMF; t++)
                #pragma unroll
                for (int u = 0; u < TNF; u++)
                    mma16816(c[t][u], a[t], b[u]);
        }
    }

    auto store = [&](int m, int n, float v) {
        if (MODE == M_QPROJ) {
            float val = (v + bias[n]) * 0.125f;
            int b_ = m >> 11, s = m & 2047, h = n >> 6, d = n & 63;
            g_qh[((long)((b_ * NHh + h) * Sq + s)) * Dh + d] = __float2half(val);
        } else if (MODE == M_KPROJ) {
            float val = v + bias[n];
            int b_ = m >> 11, s = m & 2047, h = n >> 6, d = n & 63;
            g_kh[((long)((b_ * NHh + h) * Sq + s)) * Dh + d] = __float2half(val);
        } else if (MODE == M_VPROJ) {
            float val = v + bias[n];
            int b_ = m >> 11, s = m & 2047, h = n >> 6, d = n & 63;
            long idx = ((long)((b_ * NHh + h) * Dh + d)) * Sq + s;
            __half hh = __float2half(val);
            g_vh[idx] = hh;
            g_vl[idx] = __float2half(val - __half2float(hh));
        } else if (MODE == M_SCORES) {
            long idx  = (long)g * Sq * Sq + (long)m * Sq + n;
            long midx = (long)(g >> 3) * Sq * Sq + (long)m * Sq + n;
            float val = v + attn_bias[idx];
            if (mask_true(mask, midx)) val = 0.f;
            g_xh[idx] = __float2half(val);
        } else if (MODE == M_OGEMM) {
            int b_ = g >> 3, h = g & 7;
            long idx = ((long)(b_ * Sq + m)) * HIDN + h * Dh + n;
            __half hh = __float2half(v);
            g_oh[idx] = hh;
            g_ol[idx] = __float2half(v - __half2float(hh));
        } else {  // M_OUT
            Cext[(long)m * HIDN + n] = v + bias[n];
        }
    };

    #pragma unroll
    for (int t = 0; t < TMF; t++) {
        int m = m0 + wm + t * 16 + (lane >> 2);
        #pragma unroll
        for (int u = 0; u < TNF; u++) {
            int n = n0 + wn + u * 8 + (lane & 3) * 2;
            store(m,     n,     c[t][u][0]);
            store(m,     n + 1, c[t][u][1]);
            store(m + 8, n,     c[t][u][2]);
            store(m + 8, n + 1, c[t][u][3]);
        }
    }
}

// ---------------------------------------------------------------------------
// Fused single-read softmax: g_y row (fp32) -> (ph, pl) fp16 split
// ---------------------------------------------------------------------------
__global__ void __launch_bounds__(256) softmax_kernel() {
    long row = blockIdx.x;
    const float* p = g_y + row * Sq;
    __half* oh = g_ph + row * Sq;
    __half* ol = g_pl + row * Sq;
    __shared__ float buf[Sq];
    __shared__ float red[256];
    int t = threadIdx.x;

    float mx = -3.0e38f;
    #pragma unroll
    for (int i = 0; i < Sq / 1024; i++) {
        float4 v = ((const float4*)p)[t + i * 256];
        ((float4*)buf)[t + i * 256] = v;
        mx = fmaxf(mx, fmaxf(fmaxf(v.x, v.y), fmaxf(v.z, v.w)));
    }
    red[t] = mx; __syncthreads();
    for (int s = 128; s > 0; s >>= 1) {
        if (t < s) red[t] = fmaxf(red[t], red[t + s]);
        __syncthreads();
    }
    mx = red[0];
    __syncthreads();

    float sum = 0.f;
    #pragma unroll
    for (int i = 0; i < Sq / 256; i++) {
        float e = expf(buf[t + i * 256] - mx);
        buf[t + i * 256] = e;
        sum += e;
    }
    red[t] = sum; __syncthreads();
    for (int s = 128; s > 0; s >>= 1) {
        if (t < s) red[t] += red[t + s];
        __syncthreads();
    }
    float inv = 1.f / red[0];
    __syncthreads();

    #pragma unroll
    for (int i = 0; i < Sq / 256; i++) {
        float pv = buf[t + i * 256] * inv;
        __half hh = __float2half(pv);
        oh[t + i * 256] = hh;
        ol[t + i * 256] = __float2half(pv - __half2float(hh));
    }
}

// ---------------------------------------------------------------------------
extern "C" void kernel_launch(void* const* d_in, const int* in_sizes, int n_in,
                              void* d_out, int out_size)
{
    const float* q    = (const float*)d_in[0];
    const float* k    = (const float*)d_in[1];
    const float* v    = (const float*)d_in[2];
    const float* ab   = (const float*)d_in[3];
    const void*  mask = d_in[4];
    const float* w    = (const float*)d_in[5];
    const float* Wq   = (const float*)d_in[6];
    const float* bq   = (const float*)d_in[7];
    const float* Wk   = (const float*)d_in[8];
    const float* bk   = (const float*)d_in[9];
    const float* Wv   = (const float*)d_in[10];
    const float* bv   = (const float*)d_in[11];
    const float* Wo   = (const float*)d_in[12];
    const float* bo   = (const float*)d_in[13];
    float* out = (float*)d_out;

    const int NIN = Bsz * Sq * HIDN;      // 2M
    const int NW  = HIDN * HIDN;          // 256K

    cudaFuncSetAttribute(xw2_kernel,
                         cudaFuncAttributeMaxDynamicSharedMemorySize, X2SMEM);

    detect_mask_kernel<<<1, 256>>>((const unsigned int*)mask, 65536);

    conv_half_t<C_Q> <<<NIN / 4 / 512, 512>>>(q, NIN);
    conv_half_t<C_K> <<<NIN / 4 / 512, 512>>>(k, NIN);
    conv_split_t<S_V><<<NIN / 4 / 512, 512>>>(v, NIN);
    conv_half_t<C_WQ><<<NW / 4 / 128, 128>>>(Wq, NW);
    conv_half_t<C_WK><<<NW / 4 / 128, 128>>>(Wk, NW);
    conv_split_t<S_WV><<<NW / 4 / 128, 128>>>(Wv, NW);
    conv_split_t<S_WO><<<NW / 4 / 128, 128>>>(Wo, NW);

    transpose_w_kernel<<<dim3(64, 64, Bsz), dim3(32, 8)>>>(w);

    // Projections: [4096,512] @ [512,512]^T
    hgemm<128, 128, M_QPROJ><<<dim3(4, 32, 1), 128>>>(bq, nullptr, nullptr, nullptr);
    hgemm<128, 128, M_KPROJ><<<dim3(4, 32, 1), 128>>>(bk, nullptr, nullptr, nullptr);
    hgemm<128, 128, M_VPROJ><<<dim3(4, 32, 1), 128>>>(bv, nullptr, nullptr, nullptr);

    // Scores: [2048,64]@[2048,64]^T + bias, mask -> g_xh
    hgemm<128, 128, M_SCORES><<<dim3(16, 16, GH), 128>>>(nullptr, ab, mask, nullptr);

    // y = x @ w (dominant) — XW v2
    xw2_kernel<<<dim3(16, 16, GH), 128, X2SMEM>>>();

    softmax_kernel<<<GH * Sq, 256>>>();

    // o = p @ v^T  (split 3-pass): [2048,2048]@[64,2048]^T
    hgemm<128, 64, M_OGEMM><<<dim3(1, 16, GH), 128>>>(nullptr, nullptr, nullptr, nullptr);

    // out = o @ Wo^T + bo (split 3-pass)
    hgemm<128, 128, M_OUT><<<dim3(4, 32, 1), 128>>>(bo, nullptr, nullptr, out);
}